// round 4
// baseline (speedup 1.0000x reference)
#include <cuda_runtime.h>
#include <cuda_bf16.h>
#include <cstdint>
#include <cstddef>

// ============================================================================
// AdaptiveSoftmax — mega-fused mma.sync bf16 GEMM + fixed-point base-2 sumexp
// B=4096, D=1024; head 2002; tail0: proj 256 -> 8000; tail1: proj 64 -> 40257
// ============================================================================

#define BATCH   4096
#define DMODEL  1024

#define NH_VALID 2002
#define K0       256
#define NT0_VALID 8000
#define K1       64
#define NT1_VALID 40257

#define PARTS_H  16     // 8 strips x 2 warp_n
#define PARTS_T0 18     // 9 strips x 2
#define PARTS_T1 18     // 9 strips x 2

#define NPAD_H  46
#define NPAD_T0 64
#define NPAD_T1 63

#define LOG2E 1.4426950408889634f
#define LN2   0.6931471805599453f
#define M0F   10.0f                  // fixed base-2 reference point
#define EXP2_NEG_M0 0.0009765625f    // 2^-10

// ---------------- device scratch (no allocations allowed) -------------------
__device__ __align__(256) __nv_bfloat16 g_in [BATCH * DMODEL];
__device__ __align__(256) __nv_bfloat16 g_Wh [2048 * DMODEL];
__device__ __align__(256) __nv_bfloat16 g_Wp0[256 * DMODEL];
__device__ __align__(256) __nv_bfloat16 g_Wt0[8064 * K0];
__device__ __align__(256) __nv_bfloat16 g_Wp1[128 * DMODEL];  // 64 rows padded
__device__ __align__(256) __nv_bfloat16 g_Wt1[40320 * K1];
__device__ __align__(256) __nv_bfloat16 g_p0 [BATCH * K0];
__device__ __align__(256) __nv_bfloat16 g_p1 [BATCH * K1];

__device__ float g_hs [PARTS_H  * BATCH];
__device__ float g_t0s[PARTS_T0 * BATCH];
__device__ float g_t1s[PARTS_T1 * BATCH];
__device__ float g_tgt[BATCH], g_c0[BATCH], g_c1[BATCH];

// ---------------- helpers ---------------------------------------------------
__device__ __forceinline__ uint32_t smem_u32(const void* p) {
    uint32_t a;
    asm("{ .reg .u64 t; cvta.to.shared.u64 t, %1; cvt.u32.u64 %0, t; }"
        : "=r"(a) : "l"(p));
    return a;
}

__device__ __forceinline__ float ex2f(float x) {
    float y;
    asm("ex2.approx.ftz.f32 %0, %1;" : "=f"(y) : "f"(x));
    return y;
}

// packed bf16x2 exp2: half the MUFU ops of two f32 ex2
__device__ __forceinline__ float2 exp2_pair(float x0, float x1) {
    uint32_t p, e;
    asm("cvt.rn.bf16x2.f32 %0, %1, %2;" : "=r"(p) : "f"(x1), "f"(x0));
    asm("ex2.approx.ftz.bf16x2 %0, %1;" : "=r"(e) : "r"(p));
    return make_float2(__uint_as_float(e << 16),
                       __uint_as_float(e & 0xFFFF0000u));
}

__device__ __forceinline__ void ldm_x4(uint32_t& r0, uint32_t& r1,
                                       uint32_t& r2, uint32_t& r3, uint32_t a) {
    asm volatile("ldmatrix.sync.aligned.m8n8.x4.shared.b16 {%0,%1,%2,%3}, [%4];"
                 : "=r"(r0), "=r"(r1), "=r"(r2), "=r"(r3) : "r"(a));
}

__device__ __forceinline__ void mma16816(float& d0, float& d1, float& d2, float& d3,
                                         uint32_t a0, uint32_t a1, uint32_t a2, uint32_t a3,
                                         uint32_t b0, uint32_t b1) {
    asm volatile(
        "mma.sync.aligned.m16n8k16.row.col.f32.bf16.bf16.f32 "
        "{%0,%1,%2,%3}, {%4,%5,%6,%7}, {%8,%9}, {%0,%1,%2,%3};"
        : "+f"(d0), "+f"(d1), "+f"(d2), "+f"(d3)
        : "r"(a0), "r"(a1), "r"(a2), "r"(a3), "r"(b0), "r"(b1));
}

#define CP16(dst, src) \
    asm volatile("cp.async.cg.shared.global [%0], [%1], 16;" \
                 :: "r"(dst), "l"(src) : "memory")
#define CP_COMMIT() asm volatile("cp.async.commit_group;" ::: "memory")
#define CP_WAIT0()  asm volatile("cp.async.wait_group 0;" ::: "memory")

// per-buffer geometry: 128 rows x 72 halves pitch = 18432 bytes
#define BUFB 18432u
// smem layout: [A0 A1 A2 A3][B0 B1]  (head streams A through A0/A1)
#define SMEM_MEGA (6 * 18432)
#define SMEM_PROJ (4 * 18432)

// copy one 128x64 bf16 chunk (row-major, leading dim ldk) into pitch-72 smem
__device__ __forceinline__ void cp_chunk(uint32_t dst, const __nv_bfloat16* src,
                                         int ldk, int tid) {
    #pragma unroll
    for (int i = 0; i < 4; i++) {
        int idx = tid + i * 256;
        int row = idx >> 3, seg = idx & 7;
        CP16(dst + (uint32_t)(row * 144 + seg * 16),
             src + (size_t)row * ldk + seg * 8);
    }
}

// ---------------- fused f32 -> bf16 pad-convert (all 6 arrays) ---------------
__global__ void conv_all(const float* __restrict__ in,  const float* __restrict__ Wh,
                         const float* __restrict__ Wp0, const float* __restrict__ Wt0,
                         const float* __restrict__ Wp1, const float* __restrict__ Wt1)
{
    int p = blockIdx.x * 256 + threadIdx.x;   // pair index
    const float* src; __nv_bfloat16* dst; int shift, R;
    if (p < 2097152)                   { src = in;  dst = g_in;  shift = 9; R = BATCH; }
    else if ((p -= 2097152) < 1048576) { src = Wh;  dst = g_Wh;  shift = 9; R = NH_VALID; }
    else if ((p -= 1048576) < 131072)  { src = Wp0; dst = g_Wp0; shift = 9; R = 256; }
    else if ((p -= 131072) < 1032192)  { src = Wt0; dst = g_Wt0; shift = 7; R = NT0_VALID; }
    else if ((p -= 1032192) < 65536)   { src = Wp1; dst = g_Wp1; shift = 9; R = 64; }
    else if ((p -= 65536) < 1290240)   { src = Wt1; dst = g_Wt1; shift = 5; R = NT1_VALID; }
    else return;
    int r = p >> shift;
    float2 v = (r < R) ? ((const float2*)src)[p] : make_float2(0.f, 0.f);
    ((__nv_bfloat162*)dst)[p] = __floats2bfloat162_rn(v.x, v.y);
}

// ---------------- projection GEMM (input @ Wp^T, store bf16) ------------------
// grid (3, 32): bx 0,1 -> proj0 tiles 0,1; bx 2 -> proj1 tile 0.
__global__ void __launch_bounds__(256, 2) proj_k() {
    extern __shared__ __align__(16) __nv_bfloat16 dynp[];
    const uint32_t sbase = smem_u32(dynp);

    const int tid = threadIdx.x;
    const int wid = tid >> 5, lane = tid & 31;
    const int warp_m = wid >> 1, warp_n = wid & 1;
    const int mb = blockIdx.y, bx = blockIdx.x;

    const __nv_bfloat16* Bw;
    __nv_bfloat16* outp;
    int tilecol, ldo, nstore;
    if (bx < 2) { Bw = g_Wp0 + (size_t)bx * 128 * DMODEL; outp = g_p0; tilecol = bx; ldo = 256; nstore = 256; }
    else        { Bw = g_Wp1;                             outp = g_p1; tilecol = 0;  ldo = 64;  nstore = 64; }

    const int rA = ((lane >> 3) & 1) * 8 + (lane & 7);
    const int cA = (lane >> 4) * 8;
    uint32_t offA[2];
    #pragma unroll
    for (int tm = 0; tm < 2; tm++)
        offA[tm] = (uint32_t)(((warp_m * 32 + tm * 16 + rA) * 72 + cA) * 2);

    const int rB = ((lane >> 4) & 1) * 8 + (lane & 7);
    const int cB = ((lane >> 3) & 1) * 8;
    uint32_t offB[4];
    #pragma unroll
    for (int tnp = 0; tnp < 4; tnp++)
        offB[tnp] = (uint32_t)(((warp_n * 64 + tnp * 16 + rB) * 72 + cB) * 2);

    const __nv_bfloat16* Arow = g_in + (size_t)mb * 128 * DMODEL;

    float acc[2][8][4];
    #pragma unroll
    for (int tm = 0; tm < 2; tm++)
        #pragma unroll
        for (int tn = 0; tn < 8; tn++)
            #pragma unroll
            for (int c = 0; c < 4; c++) acc[tm][tn][c] = 0.f;

    cp_chunk(sbase,             Arow, DMODEL, tid);
    cp_chunk(sbase + 2 * BUFB,  Bw,   DMODEL, tid);
    CP_COMMIT();

    for (int kc = 0; kc < 16; kc++) {
        CP_WAIT0();
        __syncthreads();
        int cur = kc & 1;
        if (kc + 1 < 16) {
            cp_chunk(sbase + (uint32_t)((kc + 1) & 1) * BUFB,
                     Arow + (kc + 1) * 64, DMODEL, tid);
            cp_chunk(sbase + 2 * BUFB + (uint32_t)((kc + 1) & 1) * BUFB,
                     Bw + (kc + 1) * 64, DMODEL, tid);
            CP_COMMIT();
        }
        uint32_t aB = sbase + (uint32_t)cur * BUFB;
        uint32_t bB = sbase + 2 * BUFB + (uint32_t)cur * BUFB;
        #pragma unroll
        for (int ks = 0; ks < 4; ks++) {
            uint32_t a[2][4], b[4][4];
            #pragma unroll
            for (int tm = 0; tm < 2; tm++)
                ldm_x4(a[tm][0], a[tm][1], a[tm][2], a[tm][3], aB + offA[tm] + ks * 32);
            #pragma unroll
            for (int tnp = 0; tnp < 4; tnp++)
                ldm_x4(b[tnp][0], b[tnp][1], b[tnp][2], b[tnp][3], bB + offB[tnp] + ks * 32);
            #pragma unroll
            for (int tm = 0; tm < 2; tm++)
                #pragma unroll
                for (int tnp = 0; tnp < 4; tnp++) {
                    mma16816(acc[tm][tnp*2+0][0], acc[tm][tnp*2+0][1],
                             acc[tm][tnp*2+0][2], acc[tm][tnp*2+0][3],
                             a[tm][0], a[tm][1], a[tm][2], a[tm][3],
                             b[tnp][0], b[tnp][1]);
                    mma16816(acc[tm][tnp*2+1][0], acc[tm][tnp*2+1][1],
                             acc[tm][tnp*2+1][2], acc[tm][tnp*2+1][3],
                             a[tm][0], a[tm][1], a[tm][2], a[tm][3],
                             b[tnp][2], b[tnp][3]);
                }
        }
    }

    int colbase = tilecol * 128 + warp_n * 64 + (lane & 3) * 2;
    #pragma unroll
    for (int s = 0; s < 4; s++) {
        int tm = s >> 1, half = s & 1;
        int grow = mb * 128 + warp_m * 32 + tm * 16 + half * 8 + (lane >> 2);
        #pragma unroll
        for (int tn = 0; tn < 8; tn++) {
            int col = colbase + tn * 8;
            if (col < nstore) {
                __nv_bfloat162 h = __floats2bfloat162_rn(
                    acc[tm][tn][half * 2 + 0], acc[tm][tn][half * 2 + 1]);
                *(__nv_bfloat162*)(outp + (size_t)grow * ldo + col) = h;
            }
        }
    }
}

// ---------------- mega: head + tail0 + tail1 fused GEMM + sumexp --------------
// grid (26, 32): bx 0..7 head strips (NPB 2), 8..16 tail0 (NPB 7), 17..25 tail1 (NPB 35)
__global__ void __launch_bounds__(256, 2) mega_lse() {
    extern __shared__ __align__(16) __nv_bfloat16 dynm[];
    const uint32_t sbase = smem_u32(dynm);

    const int tid = threadIdx.x;
    const int wid = tid >> 5, lane = tid & 31;
    const int warp_m = wid >> 1, warp_n = wid & 1;
    const int mb = blockIdx.y, bx = blockIdx.x;

    const __nv_bfloat16 *A, *Bw;
    float* Ps;
    int lda, kch, jmax, tile0, part;
    bool stream;
    if (bx < 8) {
        A = g_in;  lda = DMODEL; kch = 16; stream = true;
        Bw = g_Wh; jmax = 2;  tile0 = bx * 2;
        Ps = g_hs;  part = bx * 2 + warp_n;
    } else if (bx < 17) {
        int s = bx - 8;
        A = g_p0;  lda = K0; kch = 4; stream = false;
        Bw = g_Wt0; jmax = 7;  tile0 = s * 7;
        Ps = g_t0s; part = s * 2 + warp_n;
    } else {
        int s = bx - 17;
        A = g_p1;  lda = K1; kch = 1; stream = false;
        Bw = g_Wt1; jmax = 35; tile0 = s * 35;
        Ps = g_t1s; part = s * 2 + warp_n;
    }

    const int rA = ((lane >> 3) & 1) * 8 + (lane & 7);
    const int cA = (lane >> 4) * 8;
    uint32_t offA[2];
    #pragma unroll
    for (int tm = 0; tm < 2; tm++)
        offA[tm] = (uint32_t)(((warp_m * 32 + tm * 16 + rA) * 72 + cA) * 2);

    const int rB = ((lane >> 4) & 1) * 8 + (lane & 7);
    const int cB = ((lane >> 3) & 1) * 8;
    uint32_t offB[4];
    #pragma unroll
    for (int tnp = 0; tnp < 4; tnp++)
        offB[tnp] = (uint32_t)(((warp_n * 64 + tnp * 16 + rB) * 72 + cB) * 2);

    const __nv_bfloat16* Arow = A + (size_t)mb * 128 * lda;

    float cs[4] = {0.f, 0.f, 0.f, 0.f};

    // prologue: resident A chunks for tails; first chunk of B (and A if streaming)
    if (!stream) {
        for (int c = 0; c < kch; c++)
            cp_chunk(sbase + (uint32_t)c * BUFB, Arow + c * 64, lda, tid);
    } else {
        cp_chunk(sbase, Arow, lda, tid);
    }
    cp_chunk(sbase + 4 * BUFB, Bw + (size_t)tile0 * 128 * lda, lda, tid);
    CP_COMMIT();

    int cnt = 0;
    #pragma unroll 1
    for (int j = 0; j < jmax; j++) {
        float acc[2][8][4];
        #pragma unroll
        for (int tm = 0; tm < 2; tm++)
            #pragma unroll
            for (int tn = 0; tn < 8; tn++)
                #pragma unroll
                for (int c = 0; c < 4; c++) acc[tm][tn][c] = 0.f;

        #pragma unroll 1
        for (int kc = 0; kc < kch; kc++) {
            CP_WAIT0();
            __syncthreads();
            int cur = cnt & 1;
            cnt++;

            int jn = (kc + 1 < kch) ? j : j + 1;
            int kn = (kc + 1 < kch) ? kc + 1 : 0;
            if (jn < jmax) {
                cp_chunk(sbase + 4 * BUFB + (uint32_t)(cnt & 1) * BUFB,
                         Bw + (size_t)(tile0 + jn) * 128 * lda + kn * 64, lda, tid);
                if (stream)
                    cp_chunk(sbase + (uint32_t)(cnt & 1) * BUFB,
                             Arow + kn * 64, lda, tid);
                CP_COMMIT();
            }

            uint32_t aB = stream ? (sbase + (uint32_t)cur * BUFB)
                                 : (sbase + (uint32_t)kc * BUFB);
            uint32_t bB = sbase + 4 * BUFB + (uint32_t)cur * BUFB;

            #pragma unroll
            for (int ks = 0; ks < 4; ks++) {
                uint32_t a[2][4], b[4][4];
                #pragma unroll
                for (int tm = 0; tm < 2; tm++)
                    ldm_x4(a[tm][0], a[tm][1], a[tm][2], a[tm][3], aB + offA[tm] + ks * 32);
                #pragma unroll
                for (int tnp = 0; tnp < 4; tnp++)
                    ldm_x4(b[tnp][0], b[tnp][1], b[tnp][2], b[tnp][3], bB + offB[tnp] + ks * 32);
                #pragma unroll
                for (int tm = 0; tm < 2; tm++)
                    #pragma unroll
                    for (int tnp = 0; tnp < 4; tnp++) {
                        mma16816(acc[tm][tnp*2+0][0], acc[tm][tnp*2+0][1],
                                 acc[tm][tnp*2+0][2], acc[tm][tnp*2+0][3],
                                 a[tm][0], a[tm][1], a[tm][2], a[tm][3],
                                 b[tnp][0], b[tnp][1]);
                        mma16816(acc[tm][tnp*2+1][0], acc[tm][tnp*2+1][1],
                                 acc[tm][tnp*2+1][2], acc[tm][tnp*2+1][3],
                                 a[tm][0], a[tm][1], a[tm][2], a[tm][3],
                                 b[tnp][2], b[tnp][3]);
                    }
            }
        }

        // ---- epilogue: packed-bf16 exp2, overlaps already-issued prefetch ----
        #pragma unroll
        for (int s = 0; s < 4; s++) {
            int tm = s >> 1, half = s & 1;
            float ls = 0.f;
            #pragma unroll
            for (int tn = 0; tn < 8; tn++) {
                float x0 = fmaf(acc[tm][tn][half * 2 + 0], LOG2E, -M0F);
                float x1 = fmaf(acc[tm][tn][half * 2 + 1], LOG2E, -M0F);
                float2 e = exp2_pair(x0, x1);
                ls += e.x;
                ls += e.y;
            }
            cs[s] += ls;
        }
    }

    #pragma unroll
    for (int s = 0; s < 4; s++) {
        float sv = cs[s];
        sv += __shfl_xor_sync(0xffffffffu, sv, 1);
        sv += __shfl_xor_sync(0xffffffffu, sv, 2);
        cs[s] = sv;
    }
    if ((lane & 3) == 0) {
        #pragma unroll
        for (int s = 0; s < 4; s++) {
            int grow = mb * 128 + warp_m * 32 + (s >> 1) * 16 + (s & 1) * 8 + (lane >> 2);
            Ps[(size_t)part * BATCH + grow] = cs[s];
        }
    }
}

// ---------------- aux: target logit + head cluster cols 2000/2001 ------------
__global__ void aux_k(const int* __restrict__ target) {
    int row = blockIdx.x * 8 + (threadIdx.x >> 5);
    int lane = threadIdx.x & 31;
    if (row >= BATCH) return;

    const __nv_bfloat16* a  = g_in + (size_t)row * DMODEL;
    const __nv_bfloat16* w0 = g_Wh + (size_t)2000 * DMODEL;
    const __nv_bfloat16* w1 = g_Wh + (size_t)2001 * DMODEL;
    float s0 = 0.f, s1 = 0.f;
    #pragma unroll 4
    for (int k = lane * 2; k < DMODEL; k += 64) {
        float2 av = __bfloat1622float2(*(const __nv_bfloat162*)(a + k));
        float2 v0 = __bfloat1622float2(*(const __nv_bfloat162*)(w0 + k));
        float2 v1 = __bfloat1622float2(*(const __nv_bfloat162*)(w1 + k));
        s0 += av.x * v0.x + av.y * v0.y;
        s1 += av.x * v1.x + av.y * v1.y;
    }

    int t = target[row];
    const __nv_bfloat16 *x, *w;
    int len;
    if (t < 2000)       { x = a;                       w = g_Wh  + (size_t)t * DMODEL;       len = DMODEL; }
    else if (t < 10000) { x = g_p0 + (size_t)row * K0; w = g_Wt0 + (size_t)(t - 2000) * K0;  len = K0; }
    else                { x = g_p1 + (size_t)row * K1; w = g_Wt1 + (size_t)(t - 10000) * K1; len = K1; }
    float st = 0.f;
    for (int k = lane * 2; k < len; k += 64) {
        float2 xv = __bfloat1622float2(*(const __nv_bfloat162*)(x + k));
        float2 wv = __bfloat1622float2(*(const __nv_bfloat162*)(w + k));
        st += xv.x * wv.x + xv.y * wv.y;
    }

    #pragma unroll
    for (int d = 16; d > 0; d >>= 1) {
        s0 += __shfl_xor_sync(0xffffffffu, s0, d);
        s1 += __shfl_xor_sync(0xffffffffu, s1, d);
        st += __shfl_xor_sync(0xffffffffu, st, d);
    }
    if (lane == 0) { g_c0[row] = s0; g_c1[row] = s1; g_tgt[row] = st; }
}

// ---------------- combine partial sums -> log_p -------------------------------
__global__ void combine_k(const int* __restrict__ target, float* __restrict__ out) {
    int r = blockIdx.x * blockDim.x + threadIdx.x;
    if (r >= BATCH) return;

    float S = 0.f;
    #pragma unroll 1
    for (int i = 0; i < PARTS_H; i++) S += g_hs[i * BATCH + r];
    S -= NPAD_H * EXP2_NEG_M0;
    float lseh = LN2 * (M0F + log2f(S));

    int t = target[r];
    float res;
    if (t < 2000) {
        res = g_tgt[r] - lseh;
    } else if (t < 10000) {
        float S0 = 0.f;
        #pragma unroll 1
        for (int i = 0; i < PARTS_T0; i++) S0 += g_t0s[i * BATCH + r];
        S0 -= NPAD_T0 * EXP2_NEG_M0;
        res = (g_c0[r] - lseh) + (g_tgt[r] - LN2 * (M0F + log2f(S0)));
    } else {
        float S1 = 0.f;
        #pragma unroll 1
        for (int i = 0; i < PARTS_T1; i++) S1 += g_t1s[i * BATCH + r];
        S1 -= NPAD_T1 * EXP2_NEG_M0;
        res = (g_c1[r] - lseh) + (g_tgt[r] - LN2 * (M0F + log2f(S1)));
    }
    out[r] = res;
}

// ---------------- host --------------------------------------------------------
extern "C" void kernel_launch(void* const* d_in, const int* in_sizes, int n_in,
                              void* d_out, int out_size) {
    const float* input = (const float*)d_in[0];
    const int*   target = (const int*)d_in[1];
    const float* Wh  = (const float*)d_in[2];
    const float* Wp0 = (const float*)d_in[3];
    const float* Wt0 = (const float*)d_in[4];
    const float* Wp1 = (const float*)d_in[5];
    const float* Wt1 = (const float*)d_in[6];

    cudaFuncSetAttribute(proj_k,   cudaFuncAttributeMaxDynamicSharedMemorySize, SMEM_PROJ);
    cudaFuncSetAttribute(mega_lse, cudaFuncAttributeMaxDynamicSharedMemorySize, SMEM_MEGA);

    // 1. fused f32 -> bf16 pad-convert
    conv_all<<<22128, 256>>>(input, Wh, Wp0, Wt0, Wp1, Wt1);

    // 2. projections (tails depend on these)
    proj_k<<<dim3(3, 32), 256, SMEM_PROJ>>>();

    // 3. target + head-cluster logits (fp32 dot products)
    aux_k<<<BATCH / 8, 256>>>(target);

    // 4. mega: head + tail0 + tail1 concurrent
    mega_lse<<<dim3(26, 32), 256, SMEM_MEGA>>>();

    // 5. combine
    combine_k<<<(BATCH + 255) / 256, 256>>>(target, (float*)d_out);
}

// round 5
// speedup vs baseline: 1.0320x; 1.0320x over previous
#include <cuda_runtime.h>
#include <cuda_bf16.h>
#include <cstdint>
#include <cstddef>

// ============================================================================
// AdaptiveSoftmax — persistent mega-fused HMMA GEMM + fixed-point base-2 sumexp
// 3-stage cp.async pipeline, atomic work queue.
// ============================================================================

#define BATCH   4096
#define DMODEL  1024
#define NH_VALID 2002
#define K0       256
#define NT0_VALID 8000
#define K1       64
#define NT1_VALID 40257

#define PARTS_H  16
#define PARTS_T0 18
#define PARTS_T1 18
#define NPAD_H  46
#define NPAD_T0 64
#define NPAD_T1 63

#define NWORK_H  256    // 8 strips x 32 mb
#define NWORK_T0 288    // 9 x 32
#define NWORK_T1 288    // 9 x 32
#define NWORK    832

#define LOG2E 1.4426950408889634f
#define LN2   0.6931471805599453f
#define M0F   10.0f
#define EXP2_NEG_M0 0.0009765625f

// ---------------- device scratch --------------------------------------------
__device__ __align__(256) __nv_bfloat16 g_in [BATCH * DMODEL];
__device__ __align__(256) __nv_bfloat16 g_Wh [2048 * DMODEL];
__device__ __align__(256) __nv_bfloat16 g_Wp0[256 * DMODEL];
__device__ __align__(256) __nv_bfloat16 g_Wt0[8064 * K0];
__device__ __align__(256) __nv_bfloat16 g_Wp1[128 * DMODEL];
__device__ __align__(256) __nv_bfloat16 g_Wt1[40320 * K1];
__device__ __align__(256) __nv_bfloat16 g_p0 [BATCH * K0];
__device__ __align__(256) __nv_bfloat16 g_p1 [BATCH * K1];

__device__ float g_hs [PARTS_H  * BATCH];
__device__ float g_t0s[PARTS_T0 * BATCH];
__device__ float g_t1s[PARTS_T1 * BATCH];
__device__ int   g_work;

// ---------------- helpers ---------------------------------------------------
__device__ __forceinline__ uint32_t smem_u32(const void* p) {
    uint32_t a;
    asm("{ .reg .u64 t; cvta.to.shared.u64 t, %1; cvt.u32.u64 %0, t; }"
        : "=r"(a) : "l"(p));
    return a;
}

__device__ __forceinline__ float2 exp2_pair(float x0, float x1) {
    uint32_t p, e;
    asm("cvt.rn.bf16x2.f32 %0, %1, %2;" : "=r"(p) : "f"(x1), "f"(x0));
    asm("ex2.approx.ftz.bf16x2 %0, %1;" : "=r"(e) : "r"(p));
    return make_float2(__uint_as_float(e << 16),
                       __uint_as_float(e & 0xFFFF0000u));
}

__device__ __forceinline__ void ldm_x4(uint32_t& r0, uint32_t& r1,
                                       uint32_t& r2, uint32_t& r3, uint32_t a) {
    asm volatile("ldmatrix.sync.aligned.m8n8.x4.shared.b16 {%0,%1,%2,%3}, [%4];"
                 : "=r"(r0), "=r"(r1), "=r"(r2), "=r"(r3) : "r"(a));
}

__device__ __forceinline__ void mma16816(float& d0, float& d1, float& d2, float& d3,
                                         uint32_t a0, uint32_t a1, uint32_t a2, uint32_t a3,
                                         uint32_t b0, uint32_t b1) {
    asm volatile(
        "mma.sync.aligned.m16n8k16.row.col.f32.bf16.bf16.f32 "
        "{%0,%1,%2,%3}, {%4,%5,%6,%7}, {%8,%9}, {%0,%1,%2,%3};"
        : "+f"(d0), "+f"(d1), "+f"(d2), "+f"(d3)
        : "r"(a0), "r"(a1), "r"(a2), "r"(a3), "r"(b0), "r"(b1));
}

#define CP16(dst, src) \
    asm volatile("cp.async.cg.shared.global [%0], [%1], 16;" \
                 :: "r"(dst), "l"(src) : "memory")
#define CP_COMMIT() asm volatile("cp.async.commit_group;" ::: "memory")
#define CP_WAIT1()  asm volatile("cp.async.wait_group 1;" ::: "memory")
#define CP_WAIT0()  asm volatile("cp.async.wait_group 0;" ::: "memory")

// mega stage: A(128x64 pitch72 = 18432) + B(18432) = 36864; 3 stages
#define STG 36864u
#define SMEM_MEGA (3 * 36864 + 16)
// proj stage: A(64x72x2 = 9216) + B(18432) = 27648; 3 stages
#define PSTG 27648u
#define SMEM_PROJ (3 * 27648)

__device__ __forceinline__ void cp_chunk128(uint32_t dst, const __nv_bfloat16* src,
                                            int ldk, int tid) {
    #pragma unroll
    for (int i = 0; i < 4; i++) {
        int idx = tid + i * 256;
        int row = idx >> 3, seg = idx & 7;
        CP16(dst + (uint32_t)(row * 144 + seg * 16),
             src + (size_t)row * ldk + seg * 8);
    }
}

__device__ __forceinline__ void cp_chunk64(uint32_t dst, const __nv_bfloat16* src,
                                           int ldk, int tid) {
    #pragma unroll
    for (int i = 0; i < 2; i++) {
        int idx = tid + i * 256;
        int row = idx >> 3, seg = idx & 7;
        CP16(dst + (uint32_t)(row * 144 + seg * 16),
             src + (size_t)row * ldk + seg * 8);
    }
}

// ---------------- fused f32 -> bf16 pad-convert ------------------------------
__global__ void conv_all(const float* __restrict__ in,  const float* __restrict__ Wh,
                         const float* __restrict__ Wp0, const float* __restrict__ Wt0,
                         const float* __restrict__ Wp1, const float* __restrict__ Wt1)
{
    if (blockIdx.x == 0 && threadIdx.x == 0) g_work = 0;   // reset queue
    int p = blockIdx.x * 256 + threadIdx.x;
    const float* src; __nv_bfloat16* dst; int shift, R;
    if (p < 2097152)                   { src = in;  dst = g_in;  shift = 9; R = BATCH; }
    else if ((p -= 2097152) < 1048576) { src = Wh;  dst = g_Wh;  shift = 9; R = NH_VALID; }
    else if ((p -= 1048576) < 131072)  { src = Wp0; dst = g_Wp0; shift = 9; R = 256; }
    else if ((p -= 131072) < 1032192)  { src = Wt0; dst = g_Wt0; shift = 7; R = NT0_VALID; }
    else if ((p -= 1032192) < 65536)   { src = Wp1; dst = g_Wp1; shift = 9; R = 64; }
    else if ((p -= 65536) < 1290240)   { src = Wt1; dst = g_Wt1; shift = 5; R = NT1_VALID; }
    else return;
    int r = p >> shift;
    float2 v = (r < R) ? ((const float2*)src)[p] : make_float2(0.f, 0.f);
    ((__nv_bfloat162*)dst)[p] = __floats2bfloat162_rn(v.x, v.y);
}

// ---------------- projection GEMM: 64-row x 128-col tiles, 3-stage -----------
// grid (3, 64): bx 0,1 -> p0 col-tiles; bx 2 -> p1.
__global__ void __launch_bounds__(256, 2) proj_k() {
    extern __shared__ __align__(16) __nv_bfloat16 dynp[];
    const uint32_t sbase = smem_u32(dynp);

    const int tid = threadIdx.x;
    const int wid = tid >> 5, lane = tid & 31;
    const int warp_m = wid >> 2, warp_n = wid & 3;   // 2 x 4
    const int mb = blockIdx.y, bx = blockIdx.x;

    const __nv_bfloat16* Bw;
    __nv_bfloat16* outp;
    int tilecol, ldo, nstore;
    if (bx < 2) { Bw = g_Wp0 + (size_t)bx * 128 * DMODEL; outp = g_p0; tilecol = bx; ldo = 256; nstore = 256; }
    else        { Bw = g_Wp1;                             outp = g_p1; tilecol = 0;  ldo = 64;  nstore = 64; }

    const int rA = ((lane >> 3) & 1) * 8 + (lane & 7);
    const int cA = (lane >> 4) * 8;
    uint32_t offA[2];
    #pragma unroll
    for (int tm = 0; tm < 2; tm++)
        offA[tm] = (uint32_t)(((warp_m * 32 + tm * 16 + rA) * 72 + cA) * 2);

    const int rB = ((lane >> 4) & 1) * 8 + (lane & 7);
    const int cB = ((lane >> 3) & 1) * 8;
    uint32_t offB[2];
    #pragma unroll
    for (int tnp = 0; tnp < 2; tnp++)
        offB[tnp] = (uint32_t)(((warp_n * 32 + tnp * 16 + rB) * 72 + cB) * 2);

    const __nv_bfloat16* Arow = g_in + (size_t)mb * 64 * DMODEL;

    float acc[2][4][4];
    #pragma unroll
    for (int tm = 0; tm < 2; tm++)
        #pragma unroll
        for (int tn = 0; tn < 4; tn++)
            #pragma unroll
            for (int c = 0; c < 4; c++) acc[tm][tn][c] = 0.f;

    // prologue: stages 0,1
    #pragma unroll
    for (int cn = 0; cn < 2; cn++) {
        uint32_t st = sbase + (uint32_t)cn * PSTG;
        cp_chunk64(st, Arow + cn * 64, DMODEL, tid);
        cp_chunk128(st + 9216, Bw + cn * 64, DMODEL, tid);
        CP_COMMIT();
    }

    int stg = 0;
    #pragma unroll 1
    for (int c = 0; c < 16; c++) {
        if (c + 1 < 16) { CP_WAIT1(); } else { CP_WAIT0(); }
        __syncthreads();
        if (c + 2 < 16) {
            int si = stg + 2; if (si >= 3) si -= 3;
            uint32_t st = sbase + (uint32_t)si * PSTG;
            cp_chunk64(st, Arow + (c + 2) * 64, DMODEL, tid);
            cp_chunk128(st + 9216, Bw + (c + 2) * 64, DMODEL, tid);
            CP_COMMIT();
        }
        uint32_t aB = sbase + (uint32_t)stg * PSTG;
        uint32_t bB = aB + 9216;
        #pragma unroll
        for (int ks = 0; ks < 4; ks++) {
            uint32_t a[2][4], b[2][4];
            #pragma unroll
            for (int tm = 0; tm < 2; tm++)
                ldm_x4(a[tm][0], a[tm][1], a[tm][2], a[tm][3], aB + offA[tm] + ks * 32);
            #pragma unroll
            for (int tnp = 0; tnp < 2; tnp++)
                ldm_x4(b[tnp][0], b[tnp][1], b[tnp][2], b[tnp][3], bB + offB[tnp] + ks * 32);
            #pragma unroll
            for (int tm = 0; tm < 2; tm++)
                #pragma unroll
                for (int tnp = 0; tnp < 2; tnp++) {
                    mma16816(acc[tm][tnp*2+0][0], acc[tm][tnp*2+0][1],
                             acc[tm][tnp*2+0][2], acc[tm][tnp*2+0][3],
                             a[tm][0], a[tm][1], a[tm][2], a[tm][3],
                             b[tnp][0], b[tnp][1]);
                    mma16816(acc[tm][tnp*2+1][0], acc[tm][tnp*2+1][1],
                             acc[tm][tnp*2+1][2], acc[tm][tnp*2+1][3],
                             a[tm][0], a[tm][1], a[tm][2], a[tm][3],
                             b[tnp][2], b[tnp][3]);
                }
        }
        if (++stg == 3) stg = 0;
    }

    int colbase = tilecol * 128 + warp_n * 32 + (lane & 3) * 2;
    #pragma unroll
    for (int s = 0; s < 4; s++) {
        int tm = s >> 1, half = s & 1;
        int grow = mb * 64 + warp_m * 32 + tm * 16 + half * 8 + (lane >> 2);
        #pragma unroll
        for (int tn = 0; tn < 4; tn++) {
            int col = colbase + tn * 8;
            if (col < nstore) {
                __nv_bfloat162 h = __floats2bfloat162_rn(
                    acc[tm][tn][half * 2 + 0], acc[tm][tn][half * 2 + 1]);
                *(__nv_bfloat162*)(outp + (size_t)grow * ldo + col) = h;
            }
        }
    }
}

// ---------------- persistent mega: head + tail0 + tail1 ----------------------
__global__ void __launch_bounds__(256, 2) mega_lse() {
    extern __shared__ __align__(16) __nv_bfloat16 dynm[];
    const uint32_t sbase = smem_u32(dynm);
    int* s_w = (int*)(dynm + 3 * STG / 2);   // 16-byte tail after 3 stages

    const int tid = threadIdx.x;
    const int wid = tid >> 5, lane = tid & 31;
    const int warp_m = wid >> 1, warp_n = wid & 1;

    const int rA = ((lane >> 3) & 1) * 8 + (lane & 7);
    const int cA = (lane >> 4) * 8;
    uint32_t offA[2];
    #pragma unroll
    for (int tm = 0; tm < 2; tm++)
        offA[tm] = (uint32_t)(((warp_m * 32 + tm * 16 + rA) * 72 + cA) * 2);

    const int rB = ((lane >> 4) & 1) * 8 + (lane & 7);
    const int cB = ((lane >> 3) & 1) * 8;
    uint32_t offB[4];
    #pragma unroll
    for (int tnp = 0; tnp < 4; tnp++)
        offB[tnp] = (uint32_t)(((warp_n * 64 + tnp * 16 + rB) * 72 + cB) * 2);

    float acc[2][8][4];

    for (;;) {
        if (tid == 0) *s_w = atomicAdd(&g_work, 1);
        __syncthreads();              // broadcast w; also fences prior item's smem reads
        int w = *s_w;
        if (w >= NWORK) break;

        const __nv_bfloat16 *A, *Bw;
        float* Ps;
        int lda, kch, ksh, jmax, tile0, mb, strip;
        if (w < NWORK_H) {
            strip = w >> 5; mb = w & 31;
            A = g_in;  lda = DMODEL; kch = 16; ksh = 4;
            Bw = g_Wh; jmax = 2;  tile0 = strip * 2;  Ps = g_hs;
        } else if (w < NWORK_H + NWORK_T0) {
            int u = w - NWORK_H; strip = u >> 5; mb = u & 31;
            A = g_p0;  lda = K0; kch = 4; ksh = 2;
            Bw = g_Wt0; jmax = 7;  tile0 = strip * 7;  Ps = g_t0s;
        } else {
            int u = w - NWORK_H - NWORK_T0; strip = u >> 5; mb = u & 31;
            A = g_p1;  lda = K1; kch = 1; ksh = 0;
            Bw = g_Wt1; jmax = 35; tile0 = strip * 35; Ps = g_t1s;
        }
        const __nv_bfloat16* Arow = A + (size_t)mb * 128 * lda;
        const int total = jmax << ksh;

        // prologue: stages 0,1
        #pragma unroll 1
        for (int cn = 0; cn < 2; cn++) {
            int kcn = cn & (kch - 1), jn = cn >> ksh;
            uint32_t st = sbase + (uint32_t)cn * STG;
            cp_chunk128(st, Arow + kcn * 64, lda, tid);
            cp_chunk128(st + 18432, Bw + (size_t)(tile0 + jn) * 128 * lda + kcn * 64, lda, tid);
            CP_COMMIT();
        }

        float cs[4] = {0.f, 0.f, 0.f, 0.f};
        int stg = 0;

        #pragma unroll 1
        for (int c = 0; c < total; c++) {
            int kc = c & (kch - 1);
            if (kc == 0) {
                #pragma unroll
                for (int tm = 0; tm < 2; tm++)
                    #pragma unroll
                    for (int tn = 0; tn < 8; tn++)
                        #pragma unroll
                        for (int q = 0; q < 4; q++) acc[tm][tn][q] = 0.f;
            }

            if (c + 1 < total) { CP_WAIT1(); } else { CP_WAIT0(); }
            __syncthreads();

            if (c + 2 < total) {
                int cn = c + 2;
                int kcn = cn & (kch - 1), jn = cn >> ksh;
                int si = stg + 2; if (si >= 3) si -= 3;
                uint32_t st = sbase + (uint32_t)si * STG;
                cp_chunk128(st, Arow + kcn * 64, lda, tid);
                cp_chunk128(st + 18432, Bw + (size_t)(tile0 + jn) * 128 * lda + kcn * 64, lda, tid);
                CP_COMMIT();
            }

            uint32_t aB = sbase + (uint32_t)stg * STG;
            uint32_t bB = aB + 18432;
            #pragma unroll
            for (int ks = 0; ks < 4; ks++) {
                uint32_t a[2][4], b[4][4];
                #pragma unroll
                for (int tm = 0; tm < 2; tm++)
                    ldm_x4(a[tm][0], a[tm][1], a[tm][2], a[tm][3], aB + offA[tm] + ks * 32);
                #pragma unroll
                for (int tnp = 0; tnp < 4; tnp++)
                    ldm_x4(b[tnp][0], b[tnp][1], b[tnp][2], b[tnp][3], bB + offB[tnp] + ks * 32);
                #pragma unroll
                for (int tm = 0; tm < 2; tm++)
                    #pragma unroll
                    for (int tnp = 0; tnp < 4; tnp++) {
                        mma16816(acc[tm][tnp*2+0][0], acc[tm][tnp*2+0][1],
                                 acc[tm][tnp*2+0][2], acc[tm][tnp*2+0][3],
                                 a[tm][0], a[tm][1], a[tm][2], a[tm][3],
                                 b[tnp][0], b[tnp][1]);
                        mma16816(acc[tm][tnp*2+1][0], acc[tm][tnp*2+1][1],
                                 acc[tm][tnp*2+1][2], acc[tm][tnp*2+1][3],
                                 a[tm][0], a[tm][1], a[tm][2], a[tm][3],
                                 b[tnp][2], b[tnp][3]);
                    }
            }

            if (kc == kch - 1) {
                #pragma unroll
                for (int s = 0; s < 4; s++) {
                    int tm = s >> 1, half = s & 1;
                    float ls = 0.f;
                    #pragma unroll
                    for (int tn = 0; tn < 8; tn++) {
                        float x0 = fmaf(acc[tm][tn][half * 2 + 0], LOG2E, -M0F);
                        float x1 = fmaf(acc[tm][tn][half * 2 + 1], LOG2E, -M0F);
                        float2 e = exp2_pair(x0, x1);
                        ls += e.x;
                        ls += e.y;
                    }
                    cs[s] += ls;
                }
            }

            if (++stg == 3) stg = 0;
        }

        #pragma unroll
        for (int s = 0; s < 4; s++) {
            float sv = cs[s];
            sv += __shfl_xor_sync(0xffffffffu, sv, 1);
            sv += __shfl_xor_sync(0xffffffffu, sv, 2);
            cs[s] = sv;
        }
        int part = strip * 2 + warp_n;
        if ((lane & 3) == 0) {
            #pragma unroll
            for (int s = 0; s < 4; s++) {
                int grow = mb * 128 + warp_m * 32 + (s >> 1) * 16 + (s & 1) * 8 + (lane >> 2);
                Ps[(size_t)part * BATCH + grow] = cs[s];
            }
        }
    }
}

// ---------------- combine (+ fused aux dot products) --------------------------
// one warp per row
__global__ void combine_k(const int* __restrict__ target, float* __restrict__ out) {
    int row = (blockIdx.x * 256 + threadIdx.x) >> 5;
    int lane = threadIdx.x & 31;
    if (row >= BATCH) return;

    // head cluster cols 2000/2001
    const __nv_bfloat16* a  = g_in + (size_t)row * DMODEL;
    const __nv_bfloat16* w0 = g_Wh + (size_t)2000 * DMODEL;
    const __nv_bfloat16* w1 = g_Wh + (size_t)2001 * DMODEL;
    float s0 = 0.f, s1 = 0.f;
    #pragma unroll 4
    for (int k = lane * 2; k < DMODEL; k += 64) {
        float2 av = __bfloat1622float2(*(const __nv_bfloat162*)(a + k));
        float2 v0 = __bfloat1622float2(*(const __nv_bfloat162*)(w0 + k));
        float2 v1 = __bfloat1622float2(*(const __nv_bfloat162*)(w1 + k));
        s0 += av.x * v0.x + av.y * v0.y;
        s1 += av.x * v1.x + av.y * v1.y;
    }

    // target logit
    int t = target[row];
    const __nv_bfloat16 *x, *wv;
    int len;
    if (t < 2000)       { x = a;                       wv = g_Wh  + (size_t)t * DMODEL;       len = DMODEL; }
    else if (t < 10000) { x = g_p0 + (size_t)row * K0; wv = g_Wt0 + (size_t)(t - 2000) * K0;  len = K0; }
    else                { x = g_p1 + (size_t)row * K1; wv = g_Wt1 + (size_t)(t - 10000) * K1; len = K1; }
    float st = 0.f;
    for (int k = lane * 2; k < len; k += 64) {
        float2 xv = __bfloat1622float2(*(const __nv_bfloat162*)(x + k));
        float2 w2 = __bfloat1622float2(*(const __nv_bfloat162*)(wv + k));
        st += xv.x * w2.x + xv.y * w2.y;
    }

    // partial sums (lane-parallel)
    float Sh = (lane < PARTS_H)  ? g_hs [lane * BATCH + row] : 0.f;
    float S0 = (lane < PARTS_T0) ? g_t0s[lane * BATCH + row] : 0.f;
    float S1 = (lane < PARTS_T1) ? g_t1s[lane * BATCH + row] : 0.f;

    #pragma unroll
    for (int d = 16; d > 0; d >>= 1) {
        s0 += __shfl_xor_sync(0xffffffffu, s0, d);
        s1 += __shfl_xor_sync(0xffffffffu, s1, d);
        st += __shfl_xor_sync(0xffffffffu, st, d);
        Sh += __shfl_xor_sync(0xffffffffu, Sh, d);
        S0 += __shfl_xor_sync(0xffffffffu, S0, d);
        S1 += __shfl_xor_sync(0xffffffffu, S1, d);
    }

    if (lane == 0) {
        float lseh = LN2 * (M0F + log2f(Sh - NPAD_H * EXP2_NEG_M0));
        float res;
        if (t < 2000) {
            res = st - lseh;
        } else if (t < 10000) {
            res = (s0 - lseh) + (st - LN2 * (M0F + log2f(S0 - NPAD_T0 * EXP2_NEG_M0)));
        } else {
            res = (s1 - lseh) + (st - LN2 * (M0F + log2f(S1 - NPAD_T1 * EXP2_NEG_M0)));
        }
        out[row] = res;
    }
}

// ---------------- host --------------------------------------------------------
extern "C" void kernel_launch(void* const* d_in, const int* in_sizes, int n_in,
                              void* d_out, int out_size) {
    const float* input = (const float*)d_in[0];
    const int*   target = (const int*)d_in[1];
    const float* Wh  = (const float*)d_in[2];
    const float* Wp0 = (const float*)d_in[3];
    const float* Wt0 = (const float*)d_in[4];
    const float* Wp1 = (const float*)d_in[5];
    const float* Wt1 = (const float*)d_in[6];

    cudaFuncSetAttribute(proj_k,   cudaFuncAttributeMaxDynamicSharedMemorySize, SMEM_PROJ);
    cudaFuncSetAttribute(mega_lse, cudaFuncAttributeMaxDynamicSharedMemorySize, SMEM_MEGA);

    // 1. convert + reset work queue
    conv_all<<<22128, 256>>>(input, Wh, Wp0, Wt0, Wp1, Wt1);

    // 2. projections (64-row tiles, 192 CTAs)
    proj_k<<<dim3(3, 64), 256, SMEM_PROJ>>>();

    // 3. persistent mega (2 CTAs per SM x 148 SMs)
    mega_lse<<<296, 256, SMEM_MEGA>>>();

    // 4. combine + aux dots
    combine_k<<<512, 256>>>(target, (float*)d_out);
}

// round 8
// speedup vs baseline: 1.1427x; 1.1073x over previous
#include <cuda_runtime.h>
#include <cuda_bf16.h>
#include <cstdint>
#include <cstddef>

// ============================================================================
// AdaptiveSoftmax — persistent INT8 (s8 IMMA) GEMM + fixed-point base-2 sumexp
// input x16, weights x1024, proj x32 (powers of 2; undone in epilogue FMA).
// ============================================================================

#define BATCH   4096
#define DMODEL  1024
#define K0      256
#define K1      64

#define PARTS_H  16
#define PARTS_T0 18
#define PARTS_T1 18
#define NPAD_H  46
#define NPAD_T0 64
#define NPAD_T1 63

#define NWORK_H  256    // 8 strips x 32 mb
#define NWORK_T0 288    // 9 x 32
#define NWORK_T1 288    // 9 x 32
#define NWORK    832

#define LOG2E    1.4426950408889634f
#define LN2      0.6931471805599453f
#define M0F      10.0f
#define EXP2_NEG_M0 0.0009765625f
#define C_HEAD   (LOG2E / 16384.0f)     // 1/(16*1024)
#define C_TAIL   (LOG2E / 32768.0f)     // 1/(32*1024)
#define MAGIC_I  0x4B400000
#define MAGIC_F  12582912.0f

#define SLOT 18432u
#define SMEM_MEGA (6 * 18432 + 16)
#define PSTG 27648u
#define SMEM_PROJ (3 * 27648)

// ---------------- device scratch --------------------------------------------
__device__ __align__(256) __nv_bfloat16 g_in [BATCH * DMODEL];   // bf16 for proj
__device__ __align__(256) __nv_bfloat16 g_Wp0[256 * DMODEL];
__device__ __align__(256) __nv_bfloat16 g_Wp1[128 * DMODEL];
__device__ __align__(256) __nv_bfloat16 g_p0 [BATCH * K0];       // bf16 for combine
__device__ __align__(256) __nv_bfloat16 g_p1 [BATCH * K1];

__device__ __align__(256) uint8_t g8_in [BATCH * DMODEL];        // s8 x16
__device__ __align__(256) uint8_t g8_Wh [2048 * DMODEL];         // s8 x1024
__device__ __align__(256) uint8_t g8_Wt0[8064 * K0];
__device__ __align__(256) uint8_t g8_Wt1[40320 * K1];
__device__ __align__(256) uint8_t g8_p0 [BATCH * K0];            // s8 x32
__device__ __align__(256) uint8_t g8_p1 [BATCH * K1];

__device__ float g_hs [PARTS_H  * BATCH];
__device__ float g_t0s[PARTS_T0 * BATCH];
__device__ float g_t1s[PARTS_T1 * BATCH];
__device__ int   g_work;

// ---------------- helpers ---------------------------------------------------
__device__ __forceinline__ uint32_t smem_u32(const void* p) {
    uint32_t a;
    asm("{ .reg .u64 t; cvta.to.shared.u64 t, %1; cvt.u32.u64 %0, t; }"
        : "=r"(a) : "l"(p));
    return a;
}

__device__ __forceinline__ float2 exp2_pair(float x0, float x1) {
    uint32_t p, e;
    asm("cvt.rn.bf16x2.f32 %0, %1, %2;" : "=r"(p) : "f"(x1), "f"(x0));
    asm("ex2.approx.ftz.bf16x2 %0, %1;" : "=r"(e) : "r"(p));
    return make_float2(__uint_as_float(e << 16),
                       __uint_as_float(e & 0xFFFF0000u));
}

__device__ __forceinline__ int q8(float v, float scale) {
    int q = __float2int_rn(v * scale);
    return max(-127, min(127, q));
}

__device__ __forceinline__ void ldm_x4(uint32_t& r0, uint32_t& r1,
                                       uint32_t& r2, uint32_t& r3, uint32_t a) {
    asm volatile("ldmatrix.sync.aligned.m8n8.x4.shared.b16 {%0,%1,%2,%3}, [%4];"
                 : "=r"(r0), "=r"(r1), "=r"(r2), "=r"(r3) : "r"(a));
}

// bf16 HMMA (proj kernel)
__device__ __forceinline__ void mma_bf16(float& d0, float& d1, float& d2, float& d3,
                                         uint32_t a0, uint32_t a1, uint32_t a2, uint32_t a3,
                                         uint32_t b0, uint32_t b1) {
    asm volatile(
        "mma.sync.aligned.m16n8k16.row.col.f32.bf16.bf16.f32 "
        "{%0,%1,%2,%3}, {%4,%5,%6,%7}, {%8,%9}, {%0,%1,%2,%3};"
        : "+f"(d0), "+f"(d1), "+f"(d2), "+f"(d3)
        : "r"(a0), "r"(a1), "r"(a2), "r"(a3), "r"(b0), "r"(b1));
}

// INT8 IMMA (mega kernel) — byte layout identical to bf16 m16n8k16; sm_80+
__device__ __forceinline__ void mma_s8(int& d0, int& d1, int& d2, int& d3,
                                       uint32_t a0, uint32_t a1, uint32_t a2, uint32_t a3,
                                       uint32_t b0, uint32_t b1) {
    asm volatile(
        "mma.sync.aligned.m16n8k32.row.col.s32.s8.s8.s32 "
        "{%0,%1,%2,%3}, {%4,%5,%6,%7}, {%8,%9}, {%0,%1,%2,%3};"
        : "+r"(d0), "+r"(d1), "+r"(d2), "+r"(d3)
        : "r"(a0), "r"(a1), "r"(a2), "r"(a3), "r"(b0), "r"(b1));
}

#define CP16(dst, src) \
    asm volatile("cp.async.cg.shared.global [%0], [%1], 16;" \
                 :: "r"(dst), "l"(src) : "memory")
#define CP_COMMIT() asm volatile("cp.async.commit_group;" ::: "memory")
#define CP_WAIT1()  asm volatile("cp.async.wait_group 1;" ::: "memory")
#define CP_WAIT0()  asm volatile("cp.async.wait_group 0;" ::: "memory")

// copy 128 rows x (NSEG*16) bytes into pitched smem
template<int NSEG, int PITCH>
__device__ __forceinline__ void cp_tile(uint32_t dst, const uint8_t* src,
                                        int stride, int tid) {
    #pragma unroll
    for (int i = 0; i < NSEG / 2; i++) {
        int idx = tid + i * 256;
        int row = idx >> (NSEG == 8 ? 3 : 2);
        int seg = idx & (NSEG - 1);
        CP16(dst + (uint32_t)(row * PITCH + seg * 16),
             src + (size_t)row * stride + seg * 16);
    }
}

// ---------------- fused convert: bf16 (proj inputs) + s8 (mega inputs) -------
__global__ void conv_all(const float* __restrict__ in,  const float* __restrict__ Wh,
                         const float* __restrict__ Wp0, const float* __restrict__ Wt0,
                         const float* __restrict__ Wp1, const float* __restrict__ Wt1)
{
    if (blockIdx.x == 0 && threadIdx.x == 0) g_work = 0;
    int q = blockIdx.x * 256 + threadIdx.x;   // quad index (4 elems)
    const float* src; void* dst; int rsh, R, mode; float scale = 1.f;
    if (q < 1048576)                   { src = in;  dst = g_in;   rsh = 8; R = BATCH; mode = 0; }
    else if ((q -= 1048576) < 65536)   { src = Wp0; dst = g_Wp0;  rsh = 8; R = 256;   mode = 0; }
    else if ((q -= 65536) < 32768)     { src = Wp1; dst = g_Wp1;  rsh = 8; R = 64;    mode = 0; }
    else if ((q -= 32768) < 1048576)   { src = in;  dst = g8_in;  rsh = 8; R = BATCH; mode = 1; scale = 16.f; }
    else if ((q -= 1048576) < 524288)  { src = Wh;  dst = g8_Wh;  rsh = 8; R = 2002;  mode = 1; scale = 1024.f; }
    else if ((q -= 524288) < 516096)   { src = Wt0; dst = g8_Wt0; rsh = 6; R = 8000;  mode = 1; scale = 1024.f; }
    else if ((q -= 516096) < 645120)   { src = Wt1; dst = g8_Wt1; rsh = 4; R = 40257; mode = 1; scale = 1024.f; }
    else return;

    int r = q >> rsh;
    float4 v = (r < R) ? ((const float4*)src)[q]
                       : make_float4(0.f, 0.f, 0.f, 0.f);
    if (mode == 0) {
        uint2 o;
        __nv_bfloat162 lo = __floats2bfloat162_rn(v.x, v.y);
        __nv_bfloat162 hi = __floats2bfloat162_rn(v.z, v.w);
        o.x = *(uint32_t*)&lo; o.y = *(uint32_t*)&hi;
        ((uint2*)dst)[q] = o;
    } else {
        int q0 = q8(v.x, scale), q1 = q8(v.y, scale);
        int q2 = q8(v.z, scale), q3 = q8(v.w, scale);
        uint32_t packed = (uint32_t)(q0 & 0xFF) | ((uint32_t)(q1 & 0xFF) << 8)
                        | ((uint32_t)(q2 & 0xFF) << 16) | ((uint32_t)(q3 & 0xFF) << 24);
        ((uint32_t*)dst)[q] = packed;
    }
}

// ---------------- projection GEMM (bf16), writes bf16 + s8 outputs -----------
__global__ void __launch_bounds__(256, 2) proj_k() {
    extern __shared__ __align__(16) __nv_bfloat16 dynp[];
    const uint32_t sbase = smem_u32(dynp);

    const int tid = threadIdx.x;
    const int wid = tid >> 5, lane = tid & 31;
    const int warp_m = wid >> 2, warp_n = wid & 3;   // 2 x 4
    const int mb = blockIdx.y, bx = blockIdx.x;

    const __nv_bfloat16* Bw;
    __nv_bfloat16* outp; uint8_t* outp8;
    int tilecol, ldo, nstore;
    if (bx < 2) { Bw = g_Wp0 + (size_t)bx * 128 * DMODEL; outp = g_p0; outp8 = g8_p0; tilecol = bx; ldo = 256; nstore = 256; }
    else        { Bw = g_Wp1;                             outp = g_p1; outp8 = g8_p1; tilecol = 0;  ldo = 64;  nstore = 64; }

    const int rA = ((lane >> 3) & 1) * 8 + (lane & 7);
    const int cA = (lane >> 4) * 8;
    uint32_t offA[2];
    #pragma unroll
    for (int tm = 0; tm < 2; tm++)
        offA[tm] = (uint32_t)(((warp_m * 32 + tm * 16 + rA) * 72 + cA) * 2);

    const int rB = ((lane >> 4) & 1) * 8 + (lane & 7);
    const int cB = ((lane >> 3) & 1) * 8;
    uint32_t offB[2];
    #pragma unroll
    for (int tnp = 0; tnp < 2; tnp++)
        offB[tnp] = (uint32_t)(((warp_n * 32 + tnp * 16 + rB) * 72 + cB) * 2);

    const __nv_bfloat16* Arow = g_in + (size_t)mb * 64 * DMODEL;

    float acc[2][4][4];
    #pragma unroll
    for (int tm = 0; tm < 2; tm++)
        #pragma unroll
        for (int tn = 0; tn < 4; tn++)
            #pragma unroll
            for (int c = 0; c < 4; c++) acc[tm][tn][c] = 0.f;

    #pragma unroll
    for (int cn = 0; cn < 2; cn++) {
        uint32_t st = sbase + (uint32_t)cn * PSTG;
        cp_tile<8, 144>(st + 9216, (const uint8_t*)(Bw + cn * 64), DMODEL * 2, tid);
        #pragma unroll
        for (int i = 0; i < 2; i++) {
            int idx = tid + i * 256;
            int row = idx >> 3, seg = idx & 7;
            CP16(st + (uint32_t)(row * 144 + seg * 16),
                 (const uint8_t*)(Arow + cn * 64) + (size_t)row * DMODEL * 2 + seg * 16);
        }
        CP_COMMIT();
    }

    int stg = 0;
    #pragma unroll 1
    for (int c = 0; c < 16; c++) {
        if (c + 1 < 16) { CP_WAIT1(); } else { CP_WAIT0(); }
        __syncthreads();
        if (c + 2 < 16) {
            int si = stg + 2; if (si >= 3) si -= 3;
            uint32_t st = sbase + (uint32_t)si * PSTG;
            cp_tile<8, 144>(st + 9216, (const uint8_t*)(Bw + (c + 2) * 64), DMODEL * 2, tid);
            #pragma unroll
            for (int i = 0; i < 2; i++) {
                int idx = tid + i * 256;
                int row = idx >> 3, seg = idx & 7;
                CP16(st + (uint32_t)(row * 144 + seg * 16),
                     (const uint8_t*)(Arow + (c + 2) * 64) + (size_t)row * DMODEL * 2 + seg * 16);
            }
            CP_COMMIT();
        }
        uint32_t aB = sbase + (uint32_t)stg * PSTG;
        uint32_t bB = aB + 9216;
        #pragma unroll
        for (int ks = 0; ks < 4; ks++) {
            uint32_t a[2][4], b[2][4];
            #pragma unroll
            for (int tm = 0; tm < 2; tm++)
                ldm_x4(a[tm][0], a[tm][1], a[tm][2], a[tm][3], aB + offA[tm] + ks * 32);
            #pragma unroll
            for (int tnp = 0; tnp < 2; tnp++)
                ldm_x4(b[tnp][0], b[tnp][1], b[tnp][2], b[tnp][3], bB + offB[tnp] + ks * 32);
            #pragma unroll
            for (int tm = 0; tm < 2; tm++)
                #pragma unroll
                for (int tnp = 0; tnp < 2; tnp++) {
                    mma_bf16(acc[tm][tnp*2+0][0], acc[tm][tnp*2+0][1],
                             acc[tm][tnp*2+0][2], acc[tm][tnp*2+0][3],
                             a[tm][0], a[tm][1], a[tm][2], a[tm][3],
                             b[tnp][0], b[tnp][1]);
                    mma_bf16(acc[tm][tnp*2+1][0], acc[tm][tnp*2+1][1],
                             acc[tm][tnp*2+1][2], acc[tm][tnp*2+1][3],
                             a[tm][0], a[tm][1], a[tm][2], a[tm][3],
                             b[tnp][2], b[tnp][3]);
                }
        }
        if (++stg == 3) stg = 0;
    }

    int colbase = tilecol * 128 + warp_n * 32 + (lane & 3) * 2;
    #pragma unroll
    for (int s = 0; s < 4; s++) {
        int tm = s >> 1, half = s & 1;
        int grow = mb * 64 + warp_m * 32 + tm * 16 + half * 8 + (lane >> 2);
        #pragma unroll
        for (int tn = 0; tn < 4; tn++) {
            int col = colbase + tn * 8;
            if (col < nstore) {
                float v0 = acc[tm][tn][half * 2 + 0];
                float v1 = acc[tm][tn][half * 2 + 1];
                __nv_bfloat162 h = __floats2bfloat162_rn(v0, v1);
                *(__nv_bfloat162*)(outp + (size_t)grow * ldo + col) = h;
                int q0 = q8(v0, 32.f), q1 = q8(v1, 32.f);
                *(uint16_t*)(outp8 + (size_t)grow * ldo + col) =
                    (uint16_t)((q0 & 0xFF) | ((q1 & 0xFF) << 8));
            }
        }
    }
}

// ---------------- per-item INT8 GEMM + sumexp --------------------------------
template<int KCH, int KS, int NSEG, int PITCH, bool STREAMA>
__device__ __forceinline__ void run_item(
    uint32_t aBase, uint32_t bBase,
    const uint8_t* Arow, int lda,
    const uint8_t* Bw, int ldb, int tile0, int jmax,
    float* Ps, int strip, int mb, float Cm,
    int tid, int lane, int warp_m, int warp_n)
{
    const int CHUNKB = NSEG * 16;
    constexpr int L = (KCH == 8) ? 3 : (KCH == 2) ? 1 : 0;
    const int total = jmax * KCH;
    const float Ca = -(M0F + Cm * MAGIC_F);

    const int rA = ((lane >> 3) & 1) * 8 + (lane & 7);
    const int cAb = (lane >> 4) * 16;
    uint32_t offA[2];
    #pragma unroll
    for (int tm = 0; tm < 2; tm++)
        offA[tm] = (uint32_t)((warp_m * 32 + tm * 16 + rA) * PITCH + cAb);

    const int rB = ((lane >> 4) & 1) * 8 + (lane & 7);
    const int cBb = ((lane >> 3) & 1) * 16;
    uint32_t offB[4];
    #pragma unroll
    for (int tnp = 0; tnp < 4; tnp++)
        offB[tnp] = (uint32_t)((warp_n * 64 + tnp * 16 + rB) * PITCH + cBb);

    if (!STREAMA) {
        #pragma unroll
        for (int kc = 0; kc < KCH; kc++)
            cp_tile<NSEG, PITCH>(aBase + (uint32_t)kc * SLOT, Arow + kc * CHUNKB, lda, tid);
    }
    #pragma unroll
    for (int cn = 0; cn < 2; cn++) {
        if (STREAMA)
            cp_tile<NSEG, PITCH>(aBase + (uint32_t)cn * SLOT,
                                 Arow + (cn & (KCH - 1)) * CHUNKB, lda, tid);
        cp_tile<NSEG, PITCH>(bBase + (uint32_t)cn * SLOT,
                             Bw + (size_t)(tile0 + (cn >> L)) * 128 * ldb
                                + (cn & (KCH - 1)) * CHUNKB, ldb, tid);
        CP_COMMIT();
    }

    float cs[4] = {0.f, 0.f, 0.f, 0.f};
    int acc[2][8][4];
    int stg = 0;

    #pragma unroll 1
    for (int c = 0; c < total; c++) {
        int kc = c & (KCH - 1);
        if (kc == 0) {
            #pragma unroll
            for (int tm = 0; tm < 2; tm++)
                #pragma unroll
                for (int tn = 0; tn < 8; tn++)
                    #pragma unroll
                    for (int q = 0; q < 4; q++) acc[tm][tn][q] = 0;
        }

        if (c + 1 < total) { CP_WAIT1(); } else { CP_WAIT0(); }
        __syncthreads();

        if (c + 2 < total) {
            int cn = c + 2;
            int si = stg + 2; if (si >= 3) si -= 3;
            if (STREAMA)
                cp_tile<NSEG, PITCH>(aBase + (uint32_t)si * SLOT,
                                     Arow + (cn & (KCH - 1)) * CHUNKB, lda, tid);
            cp_tile<NSEG, PITCH>(bBase + (uint32_t)si * SLOT,
                                 Bw + (size_t)(tile0 + (cn >> L)) * 128 * ldb
                                    + (cn & (KCH - 1)) * CHUNKB, ldb, tid);
            CP_COMMIT();
        }

        uint32_t aB = STREAMA ? (aBase + (uint32_t)stg * SLOT)
                              : (aBase + (uint32_t)kc * SLOT);
        uint32_t bB = bBase + (uint32_t)stg * SLOT;

        #pragma unroll
        for (int ks = 0; ks < KS; ks++) {
            uint32_t a[2][4], b[4][4];
            #pragma unroll
            for (int tm = 0; tm < 2; tm++)
                ldm_x4(a[tm][0], a[tm][1], a[tm][2], a[tm][3], aB + offA[tm] + ks * 32);
            #pragma unroll
            for (int tnp = 0; tnp < 4; tnp++)
                ldm_x4(b[tnp][0], b[tnp][1], b[tnp][2], b[tnp][3], bB + offB[tnp] + ks * 32);
            #pragma unroll
            for (int tm = 0; tm < 2; tm++)
                #pragma unroll
                for (int tnp = 0; tnp < 4; tnp++) {
                    mma_s8(acc[tm][tnp*2+0][0], acc[tm][tnp*2+0][1],
                           acc[tm][tnp*2+0][2], acc[tm][tnp*2+0][3],
                           a[tm][0], a[tm][1], a[tm][2], a[tm][3],
                           b[tnp][0], b[tnp][1]);
                    mma_s8(acc[tm][tnp*2+1][0], acc[tm][tnp*2+1][1],
                           acc[tm][tnp*2+1][2], acc[tm][tnp*2+1][3],
                           a[tm][0], a[tm][1], a[tm][2], a[tm][3],
                           b[tnp][2], b[tnp][3]);
                }
        }

        if (kc == KCH - 1) {
            #pragma unroll
            for (int s = 0; s < 4; s++) {
                int tm = s >> 1, half = s & 1;
                float ls = 0.f;
                #pragma unroll
                for (int tn = 0; tn < 8; tn++) {
                    float f0 = __int_as_float(acc[tm][tn][half * 2 + 0] + MAGIC_I);
                    float f1 = __int_as_float(acc[tm][tn][half * 2 + 1] + MAGIC_I);
                    float2 e = exp2_pair(fmaf(f0, Cm, Ca), fmaf(f1, Cm, Ca));
                    ls += e.x;
                    ls += e.y;
                }
                cs[s] += ls;
            }
        }

        if (++stg == 3) stg = 0;
    }

    #pragma unroll
    for (int s = 0; s < 4; s++) {
        float sv = cs[s];
        sv += __shfl_xor_sync(0xffffffffu, sv, 1);
        sv += __shfl_xor_sync(0xffffffffu, sv, 2);
        cs[s] = sv;
    }
    int part = strip * 2 + warp_n;
    if ((lane & 3) == 0) {
        #pragma unroll
        for (int s = 0; s < 4; s++) {
            int grow = mb * 128 + warp_m * 32 + (s >> 1) * 16 + (s & 1) * 8 + (lane >> 2);
            Ps[(size_t)part * BATCH + grow] = cs[s];
        }
    }
}

// ---------------- persistent mega -------------------------------------------
__global__ void __launch_bounds__(256, 2) mega_lse() {
    extern __shared__ __align__(16) __nv_bfloat16 dynm[];
    const uint32_t sbase = smem_u32(dynm);
    int* s_w = (int*)((char*)dynm + 6 * SLOT);

    const int tid = threadIdx.x;
    const int wid = tid >> 5, lane = tid & 31;
    const int warp_m = wid >> 1, warp_n = wid & 1;
    const uint32_t aBase = sbase, bBase = sbase + 3 * SLOT;

    for (;;) {
        if (tid == 0) *s_w = atomicAdd(&g_work, 1);
        __syncthreads();
        int w = *s_w;
        if (w >= NWORK) break;

        if (w < NWORK_H) {
            int strip = w >> 5, mb = w & 31;
            run_item<8, 4, 8, 144, true>(aBase, bBase,
                g8_in + (size_t)mb * 128 * DMODEL, DMODEL,
                g8_Wh, DMODEL, strip * 2, 2,
                g_hs, strip, mb, C_HEAD, tid, lane, warp_m, warp_n);
        } else if (w < NWORK_H + NWORK_T0) {
            int u = w - NWORK_H, strip = u >> 5, mb = u & 31;
            run_item<2, 4, 8, 144, false>(aBase, bBase,
                g8_p0 + (size_t)mb * 128 * K0, K0,
                g8_Wt0, K0, strip * 7, 7,
                g_t0s, strip, mb, C_TAIL, tid, lane, warp_m, warp_n);
        } else {
            int u = w - NWORK_H - NWORK_T0, strip = u >> 5, mb = u & 31;
            run_item<1, 2, 4, 80, false>(aBase, bBase,
                g8_p1 + (size_t)mb * 128 * K1, K1,
                g8_Wt1, K1, strip * 35, 35,
                g_t1s, strip, mb, C_TAIL, tid, lane, warp_m, warp_n);
        }
    }
}

// ---------------- combine: f32 aux dots + partial-sum reduction ---------------
__global__ void combine_k(const int* __restrict__ target, float* __restrict__ out,
                          const float* __restrict__ inF, const float* __restrict__ WhF,
                          const float* __restrict__ Wt0F, const float* __restrict__ Wt1F)
{
    int row = (blockIdx.x * 256 + threadIdx.x) >> 5;
    int lane = threadIdx.x & 31;
    if (row >= BATCH) return;

    const float* a  = inF + (size_t)row * DMODEL;
    const float* w0 = WhF + (size_t)2000 * DMODEL;
    const float* w1 = WhF + (size_t)2001 * DMODEL;
    float s0 = 0.f, s1 = 0.f;
    #pragma unroll 2
    for (int k = lane * 4; k < DMODEL; k += 128) {
        float4 av = *(const float4*)(a + k);
        float4 v0 = *(const float4*)(w0 + k);
        float4 v1 = *(const float4*)(w1 + k);
        s0 += av.x * v0.x + av.y * v0.y + av.z * v0.z + av.w * v0.w;
        s1 += av.x * v1.x + av.y * v1.y + av.z * v1.z + av.w * v1.w;
    }

    int t = target[row];
    float st = 0.f;
    if (t < 2000) {
        const float* wt = WhF + (size_t)t * DMODEL;
        #pragma unroll 2
        for (int k = lane * 4; k < DMODEL; k += 128) {
            float4 av = *(const float4*)(a + k);
            float4 wv = *(const float4*)(wt + k);
            st += av.x * wv.x + av.y * wv.y + av.z * wv.z + av.w * wv.w;
        }
    } else if (t < 10000) {
        const __nv_bfloat16* p = g_p0 + (size_t)row * K0;
        const float* wt = Wt0F + (size_t)(t - 2000) * K0;
        for (int k = lane * 2; k < K0; k += 64) {
            float2 pv = __bfloat1622float2(*(const __nv_bfloat162*)(p + k));
            float2 wv = *(const float2*)(wt + k);
            st += pv.x * wv.x + pv.y * wv.y;
        }
    } else {
        const __nv_bfloat16* p = g_p1 + (size_t)row * K1;
        const float* wt = Wt1F + (size_t)(t - 10000) * K1;
        for (int k = lane * 2; k < K1; k += 64) {
            float2 pv = __bfloat1622float2(*(const __nv_bfloat162*)(p + k));
            float2 wv = *(const float2*)(wt + k);
            st += pv.x * wv.x + pv.y * wv.y;
        }
    }

    float Sh = (lane < PARTS_H)  ? g_hs [lane * BATCH + row] : 0.f;
    float S0 = (lane < PARTS_T0) ? g_t0s[lane * BATCH + row] : 0.f;
    float S1 = (lane < PARTS_T1) ? g_t1s[lane * BATCH + row] : 0.f;

    #pragma unroll
    for (int d = 16; d > 0; d >>= 1) {
        s0 += __shfl_xor_sync(0xffffffffu, s0, d);
        s1 += __shfl_xor_sync(0xffffffffu, s1, d);
        st += __shfl_xor_sync(0xffffffffu, st, d);
        Sh += __shfl_xor_sync(0xffffffffu, Sh, d);
        S0 += __shfl_xor_sync(0xffffffffu, S0, d);
        S1 += __shfl_xor_sync(0xffffffffu, S1, d);
    }

    if (lane == 0) {
        float lseh = LN2 * (M0F + log2f(Sh - NPAD_H * EXP2_NEG_M0));
        float res;
        if (t < 2000) {
            res = st - lseh;
        } else if (t < 10000) {
            res = (s0 - lseh) + (st - LN2 * (M0F + log2f(S0 - NPAD_T0 * EXP2_NEG_M0)));
        } else {
            res = (s1 - lseh) + (st - LN2 * (M0F + log2f(S1 - NPAD_T1 * EXP2_NEG_M0)));
        }
        out[row] = res;
    }
}

// ---------------- host --------------------------------------------------------
extern "C" void kernel_launch(void* const* d_in, const int* in_sizes, int n_in,
                              void* d_out, int out_size) {
    const float* input = (const float*)d_in[0];
    const int*   target = (const int*)d_in[1];
    const float* Wh  = (const float*)d_in[2];
    const float* Wp0 = (const float*)d_in[3];
    const float* Wt0 = (const float*)d_in[4];
    const float* Wp1 = (const float*)d_in[5];
    const float* Wt1 = (const float*)d_in[6];

    cudaFuncSetAttribute(proj_k,   cudaFuncAttributeMaxDynamicSharedMemorySize, SMEM_PROJ);
    cudaFuncSetAttribute(mega_lse, cudaFuncAttributeMaxDynamicSharedMemorySize, SMEM_MEGA);

    // 1. convert (bf16 for proj/combine, s8 for mega) + queue reset
    conv_all<<<15160, 256>>>(input, Wh, Wp0, Wt0, Wp1, Wt1);

    // 2. projections (bf16 MMA; writes bf16 + s8 outputs)
    proj_k<<<dim3(3, 64), 256, SMEM_PROJ>>>();

    // 3. persistent INT8 mega
    mega_lse<<<296, 256, SMEM_MEGA>>>();

    // 4. combine (f32 aux dots against original inputs)
    combine_k<<<512, 256>>>(target, (float*)d_out, input, Wh, Wt0, Wt1);
}